// round 8
// baseline (speedup 1.0000x reference)
#include <cuda_runtime.h>
#include <math.h>

#define FULL 0xffffffffu
#define T_STEPS 32
#define BATCH   128
#define NQ      8

// Closed-form QLSTM (derived R2, verified):
//   <Z_w> = prod_{k=0..w} cos(theta_k)*cos(q_k)  (w>=1);  <Z_0> = prod_{k=1..7} ...
// q = W [x;h] + b (first 8 rows), and q is IDENTICAL for all 4 circuits.
// => per step compute Q_j = masked prod of cos(q_k) once; each circuit's
// expectation is Cpref_c[j] * Q_j with Cpref a per-lane constant (sigmoid 1/2 folded).

__device__ __forceinline__ float tanh_ap(float x) {
    float y;
    asm("tanh.approx.f32 %0, %1;" : "=f"(y) : "f"(x));
    return y;
}

__device__ __forceinline__ void bar_arrive(int id, int cnt) {
    asm volatile("bar.arrive %0, %1;" :: "r"(id), "r"(cnt));
}
__device__ __forceinline__ void bar_sync_named(int id, int cnt) {
    asm volatile("bar.sync %0, %1;" :: "r"(id), "r"(cnt) : "memory");
}

// Block = 160 threads. Warp 0: recurrence; every lane owns unit j = lane&7 with
// ALL 4 gates local (groups of 8 are redundant replicas -> no cross-circuit
// shuffle). Warps 1-4: producers; warp w computes qx[t][:] for t in [(w-1)*8, w*8).
__global__ void __launch_bounds__(160, 1) qlstm_kernel(
    const float* __restrict__ x,   // [32,128,64]
    const float* __restrict__ W,   // [16,72]
    const float* __restrict__ bv,  // [16]
    const float* __restrict__ fp, const float* __restrict__ ip,
    const float* __restrict__ up, const float* __restrict__ op,
    float* __restrict__ out) {

    __shared__ float s_qx[T_STEPS * NQ];

    int tid  = threadIdx.x;
    int lane = tid & 31;
    int wid  = tid >> 5;
    int b    = blockIdx.x;
    int j    = lane & 7;
    int gb   = lane & 24;

    if (wid >= 1) {
        // ---- producer warp: qx[t][j] = b_j + W_x[j,:] . x[t,b,:] ----
        int cc = lane >> 3;   // k-slice
        const float4* wxp = (const float4*)(W + j * 72 + 16 * cc);
        float4 w0 = wxp[0], w1 = wxp[1], w2 = wxp[2], w3 = wxp[3];
        float bj = bv[j];
        int t0 = (wid - 1) * 8;
        #pragma unroll
        for (int tt = 0; tt < 8; ++tt) {
            int t = t0 + tt;
            const float4* xp = (const float4*)(x + (t * BATCH + b) * 64 + 16 * cc);
            float4 v0 = xp[0], v1 = xp[1], v2 = xp[2], v3 = xp[3];
            float p0 = w0.x * v0.x + w0.y * v0.y + w0.z * v0.z + w0.w * v0.w;
            float p1 = w1.x * v1.x + w1.y * v1.y + w1.z * v1.z + w1.w * v1.w;
            float p2 = w2.x * v2.x + w2.y * v2.y + w2.z * v2.z + w2.w * v2.w;
            float p3 = w3.x * v3.x + w3.y * v3.y + w3.z * v3.z + w3.w * v3.w;
            float part = (p0 + p1) + (p2 + p3);
            part += __shfl_xor_sync(FULL, part, 8);
            part += __shfl_xor_sync(FULL, part, 16);
            if (cc == 0) s_qx[t * NQ + j] = part + bj;
        }
        __threadfence_block();
        bar_arrive(wid, 64);
        return;
    }

    // ---- recurrence warp setup (overlaps producers) ----
    const float4* whp = (const float4*)(W + j * 72 + 64);
    float4 wa = whp[0], wb4 = whp[1];

    bool j0 = (j == 0);
    bool m0 = !j0;
    bool m2 = j0 || (2 <= j), m3 = j0 || (3 <= j), m4 = j0 || (4 <= j);
    bool m5 = j0 || (5 <= j), m6 = j0 || (6 <= j), m7 = j0 || (j == 7);

    // masked-product fan helper (over this lane's group of 8)
    #define MASKED_TREE(res, val)                                        \
        {                                                                \
            float q0 = __shfl_sync(FULL, (val), gb | 0);                 \
            float q1 = __shfl_sync(FULL, (val), gb | 1);                 \
            float q2 = __shfl_sync(FULL, (val), gb | 2);                 \
            float q3 = __shfl_sync(FULL, (val), gb | 3);                 \
            float q4 = __shfl_sync(FULL, (val), gb | 4);                 \
            float q5 = __shfl_sync(FULL, (val), gb | 5);                 \
            float q6 = __shfl_sync(FULL, (val), gb | 6);                 \
            float q7 = __shfl_sync(FULL, (val), gb | 7);                 \
            float a0 = m0 ? q0 : 1.f;                                    \
            float a2 = m2 ? q2 : 1.f;                                    \
            float a3 = m3 ? q3 : 1.f;                                    \
            float a4 = m4 ? q4 : 1.f;                                    \
            float a5 = m5 ? q5 : 1.f;                                    \
            float a6 = m6 ? q6 : 1.f;                                    \
            float a7 = m7 ? q7 : 1.f;                                    \
            res = ((a0 * q1) * (a2 * a3)) * ((a4 * a5) * (a6 * a7));     \
        }

    // per-lane Cpref for all 4 circuits (theta prefix; sigmoid 1/2 folded in)
    float cf = __cosf(fp[j]);
    float ci = __cosf(ip[j]);
    float cu = __cosf(up[j]);
    float co = __cosf(op[j]);
    float Cf, Ci, Cu, Co;
    MASKED_TREE(Cf, cf); Cf *= 0.5f;
    MASKED_TREE(Ci, ci); Ci *= 0.5f;
    MASKED_TREE(Cu, cu);
    MASKED_TREE(Co, co); Co *= 0.5f;

    float h = 0.f, cstate = 0.f;
    bool store_lane = (gb == 0);

    #pragma unroll 1
    for (int seg = 0; seg < 4; ++seg) {
        bar_sync_named(seg + 1, 64);   // producer warp seg+1 landed its qx range

        #pragma unroll
        for (int tt = 0; tt < 8; ++tt) {
            int t = seg * 8 + tt;
            float qx = s_qx[t * NQ + j];   // off-chain LDS, latency hidden

            // ---- CHAIN stage 1: h fan-out + dot + cos ----
            float h0 = __shfl_sync(FULL, h, gb | 0);
            float h1 = __shfl_sync(FULL, h, gb | 1);
            float h2 = __shfl_sync(FULL, h, gb | 2);
            float h3 = __shfl_sync(FULL, h, gb | 3);
            float h4 = __shfl_sync(FULL, h, gb | 4);
            float h5 = __shfl_sync(FULL, h, gb | 5);
            float h6 = __shfl_sync(FULL, h, gb | 6);
            float h7 = __shfl_sync(FULL, h, gb | 7);
            float s01 = wa.x  * h0 + wa.y  * h1;
            float s23 = wa.z  * h2 + wa.w  * h3;
            float s45 = wb4.x * h4 + wb4.y * h5;
            float s67 = wb4.z * h6 + wb4.w * h7;
            float th  = (qx + (s01 + s23)) + (s45 + s67);
            float cq  = __cosf(th);

            // ---- CHAIN stage 2: gather cos q, masked product Q_j ----
            float Q;
            MASKED_TREE(Q, cq);

            // ---- all 4 gates local (no cross-circuit shuffle) ----
            float f = fmaf(0.5f, tanh_ap(Cf * Q), 0.5f);
            float i = fmaf(0.5f, tanh_ap(Ci * Q), 0.5f);
            float g = tanh_ap(Cu * Q);
            float o = fmaf(0.5f, tanh_ap(Co * Q), 0.5f);

            cstate = fmaf(f, cstate, i * g);
            h = o * tanh_ap(cstate);

            if (store_lane) out[(t * BATCH + b) * NQ + j] = h;
        }
    }

    if (store_lane) {
        out[T_STEPS * BATCH * NQ + b * NQ + j]              = h;       // hx
        out[T_STEPS * BATCH * NQ + BATCH * NQ + b * NQ + j] = cstate;  // cx
    }
    #undef MASKED_TREE
}

extern "C" void kernel_launch(void* const* d_in, const int* in_sizes, int n_in,
                              void* d_out, int out_size) {
    const float* x  = (const float*)d_in[0];
    const float* W  = (const float*)d_in[1];
    const float* bv = (const float*)d_in[2];
    const float* fp = (const float*)d_in[3];
    const float* ip = (const float*)d_in[4];
    const float* up = (const float*)d_in[5];
    const float* op = (const float*)d_in[6];
    float* out = (float*)d_out;

    qlstm_kernel<<<BATCH, 160>>>(x, W, bv, fp, ip, up, op, out);
}

// round 9
// speedup vs baseline: 1.1069x; 1.1069x over previous
#include <cuda_runtime.h>
#include <math.h>

#define FULL 0xffffffffu
#define T_STEPS 32
#define BATCH   128
#define NQ      8

// Closed-form QLSTM (derived R2, verified):
//   <Z_w> = prod_{k=0..w} cos(theta_k)*cos(q_k)  (w>=1);  <Z_0> = prod_{k=1..7} ...
// q = W [x;h] + b (first 8 rows), identical for all 4 circuits.
// Per step: Q_j = masked prod of cos(q_k); gate_c = nonlin(Cpref_c[j] * Q_j).
// This round: cross-lane exchanges via SMEM (STS/syncwarp/LDS.128) instead of
// SHFL fans — single-variable experiment on SHFL latency.

__device__ __forceinline__ float tanh_ap(float x) {
    float y;
    asm("tanh.approx.f32 %0, %1;" : "=f"(y) : "f"(x));
    return y;
}

__device__ __forceinline__ void bar_arrive(int id, int cnt) {
    asm volatile("bar.arrive %0, %1;" :: "r"(id), "r"(cnt));
}
__device__ __forceinline__ void bar_sync_named(int id, int cnt) {
    asm volatile("bar.sync %0, %1;" :: "r"(id), "r"(cnt) : "memory");
}

// Block = 160 threads. Warp 0: recurrence (lane&7 = unit j; all 4 gates local).
// Warps 1-4: producers; warp w computes qx[t][:] for t in [(w-1)*8, w*8).
__global__ void __launch_bounds__(160, 1) qlstm_kernel(
    const float* __restrict__ x,   // [32,128,64]
    const float* __restrict__ W,   // [16,72]
    const float* __restrict__ bv,  // [16]
    const float* __restrict__ fp, const float* __restrict__ ip,
    const float* __restrict__ up, const float* __restrict__ op,
    float* __restrict__ out) {

    __shared__ float s_qx[T_STEPS * NQ];
    __shared__ __align__(16) float s_h[8];
    __shared__ __align__(16) float s_cq[8];

    int tid  = threadIdx.x;
    int lane = tid & 31;
    int wid  = tid >> 5;
    int b    = blockIdx.x;
    int j    = lane & 7;
    int gb   = lane & 24;

    if (wid >= 1) {
        // ---- producer warp: qx[t][j] = b_j + W_x[j,:] . x[t,b,:] ----
        int cc = lane >> 3;   // k-slice
        const float4* wxp = (const float4*)(W + j * 72 + 16 * cc);
        float4 w0 = wxp[0], w1 = wxp[1], w2 = wxp[2], w3 = wxp[3];
        float bj = bv[j];
        int t0 = (wid - 1) * 8;
        #pragma unroll
        for (int tt = 0; tt < 8; ++tt) {
            int t = t0 + tt;
            const float4* xp = (const float4*)(x + (t * BATCH + b) * 64 + 16 * cc);
            float4 v0 = xp[0], v1 = xp[1], v2 = xp[2], v3 = xp[3];
            float p0 = w0.x * v0.x + w0.y * v0.y + w0.z * v0.z + w0.w * v0.w;
            float p1 = w1.x * v1.x + w1.y * v1.y + w1.z * v1.z + w1.w * v1.w;
            float p2 = w2.x * v2.x + w2.y * v2.y + w2.z * v2.z + w2.w * v2.w;
            float p3 = w3.x * v3.x + w3.y * v3.y + w3.z * v3.z + w3.w * v3.w;
            float part = (p0 + p1) + (p2 + p3);
            part += __shfl_xor_sync(FULL, part, 8);
            part += __shfl_xor_sync(FULL, part, 16);
            if (cc == 0) s_qx[t * NQ + j] = part + bj;
        }
        __threadfence_block();
        bar_arrive(wid, 64);
        return;
    }

    // ---- recurrence warp setup (overlaps producers) ----
    const float4* whp = (const float4*)(W + j * 72 + 64);
    float4 wa = whp[0], wb4 = whp[1];

    bool j0 = (j == 0);
    bool m0 = !j0;
    bool m2 = j0 || (2 <= j), m3 = j0 || (3 <= j), m4 = j0 || (4 <= j);
    bool m5 = j0 || (5 <= j), m6 = j0 || (6 <= j), m7 = j0 || (j == 7);

    // one-time Cpref via shfl fan (prologue; overlapped with producers)
    #define MASKED_TREE(res, val)                                        \
        {                                                                \
            float q0 = __shfl_sync(FULL, (val), gb | 0);                 \
            float q1 = __shfl_sync(FULL, (val), gb | 1);                 \
            float q2 = __shfl_sync(FULL, (val), gb | 2);                 \
            float q3 = __shfl_sync(FULL, (val), gb | 3);                 \
            float q4 = __shfl_sync(FULL, (val), gb | 4);                 \
            float q5 = __shfl_sync(FULL, (val), gb | 5);                 \
            float q6 = __shfl_sync(FULL, (val), gb | 6);                 \
            float q7 = __shfl_sync(FULL, (val), gb | 7);                 \
            float a0 = m0 ? q0 : 1.f;                                    \
            float a2 = m2 ? q2 : 1.f;                                    \
            float a3 = m3 ? q3 : 1.f;                                    \
            float a4 = m4 ? q4 : 1.f;                                    \
            float a5 = m5 ? q5 : 1.f;                                    \
            float a6 = m6 ? q6 : 1.f;                                    \
            float a7 = m7 ? q7 : 1.f;                                    \
            res = ((a0 * q1) * (a2 * a3)) * ((a4 * a5) * (a6 * a7));     \
        }

    float cf = __cosf(fp[j]);
    float ci = __cosf(ip[j]);
    float cu = __cosf(up[j]);
    float co = __cosf(op[j]);
    float Cf, Ci, Cu, Co;
    MASKED_TREE(Cf, cf); Cf *= 0.5f;
    MASKED_TREE(Ci, ci); Ci *= 0.5f;
    MASKED_TREE(Cu, cu);
    MASKED_TREE(Co, co); Co *= 0.5f;
    #undef MASKED_TREE

    bool store8 = (lane < 8);
    if (store8) s_h[j] = 0.f;       // h(t=-1) = 0
    __syncwarp();

    float h = 0.f, cstate = 0.f;

    #pragma unroll 1
    for (int seg = 0; seg < 4; ++seg) {
        bar_sync_named(seg + 1, 64);   // producer warp seg+1 landed its qx range

        #pragma unroll
        for (int tt = 0; tt < 8; ++tt) {
            int t = seg * 8 + tt;
            float qx = s_qx[t * NQ + j];   // off-chain LDS

            // ---- exchange h via SMEM (s_h already holds h(t-1); see tail STS) ----
            float4 hA = *(const float4*)&s_h[0];
            float4 hB = *(const float4*)&s_h[4];
            float s01 = wa.x  * hA.x + wa.y  * hA.y;
            float s23 = wa.z  * hA.z + wa.w  * hA.w;
            float s45 = wb4.x * hB.x + wb4.y * hB.y;
            float s67 = wb4.z * hB.z + wb4.w * hB.w;
            float th  = (qx + (s01 + s23)) + (s45 + s67);
            float cq  = __cosf(th);

            // ---- exchange cq via SMEM ----
            if (store8) s_cq[j] = cq;
            __syncwarp();
            float4 qA = *(const float4*)&s_cq[0];
            float4 qB = *(const float4*)&s_cq[4];

            float a0 = m0 ? qA.x : 1.f;
            float a2 = m2 ? qA.z : 1.f;
            float a3 = m3 ? qA.w : 1.f;
            float a4 = m4 ? qB.x : 1.f;
            float a5 = m5 ? qB.y : 1.f;
            float a6 = m6 ? qB.z : 1.f;
            float a7 = m7 ? qB.w : 1.f;
            float Q = ((a0 * qA.y) * (a2 * a3)) * ((a4 * a5) * (a6 * a7));

            // ---- all 4 gates local ----
            float f = fmaf(0.5f, tanh_ap(Cf * Q), 0.5f);
            float i = fmaf(0.5f, tanh_ap(Ci * Q), 0.5f);
            float g = tanh_ap(Cu * Q);
            float o = fmaf(0.5f, tanh_ap(Co * Q), 0.5f);

            cstate = fmaf(f, cstate, i * g);
            h = o * tanh_ap(cstate);

            // publish h(t) for next step (syncwarp doubles as release fence)
            if (store8) s_h[j] = h;
            __syncwarp();

            if (store8) out[(t * BATCH + b) * NQ + j] = h;
        }
    }

    if (store8) {
        out[T_STEPS * BATCH * NQ + b * NQ + j]              = h;       // hx
        out[T_STEPS * BATCH * NQ + BATCH * NQ + b * NQ + j] = cstate;  // cx
    }
}

extern "C" void kernel_launch(void* const* d_in, const int* in_sizes, int n_in,
                              void* d_out, int out_size) {
    const float* x  = (const float*)d_in[0];
    const float* W  = (const float*)d_in[1];
    const float* bv = (const float*)d_in[2];
    const float* fp = (const float*)d_in[3];
    const float* ip = (const float*)d_in[4];
    const float* up = (const float*)d_in[5];
    const float* op = (const float*)d_in[6];
    float* out = (float*)d_out;

    qlstm_kernel<<<BATCH, 160>>>(x, W, bv, fp, ip, up, op, out);
}